// round 8
// baseline (speedup 1.0000x reference)
#include <cuda_runtime.h>
#include <cstdint>

// Shapes (fixed by the problem instance)
#define BNTOT 828      // B*N = 4*207
#define LDIM 96
#define SDIM 96
#define HDIM 8
#define EDIM 64
#define DDIM 64

#define TL   32        // l-rows per CTA (3 tiles)
#define SC   16        // s-chunk size (6 chunks)
#define NCH  6

#define LPAD 36        // Q  smem row stride  [h][e][LPAD]
#define KSP  20        // K  smem row stride  [h][e][KSP]
#define VSP  68        // V  smem row stride  [h][s][VSP]
#define SP   97        // P  smem row stride  [h][l][SP]

// smem float offsets
#define QS_OFF 0
#define QS_SZ  (HDIM*EDIM*LPAD)          // 18432
#define KS_OFF (QS_OFF + QS_SZ)
#define KS_SZ  (HDIM*EDIM*KSP)           // 10240 (>= Vs: 8*16*68 = 8704)
#define P_OFF  (KS_OFF + KS_SZ)          // 28672
#define P_SZ   (HDIM*TL*SP)              // 24832
#define GB_OFF (P_OFF + P_SZ)            // 53504
#define SMEM_FLOATS (GB_OFF + 16)        // 53520
#define SMEM_BYTES  (SMEM_FLOATS * 4)    // 214080 B  (< 227KB opt-in)

#define SCORES_ELEMS ((size_t)BNTOT * HDIM * LDIM * SDIM)   // 61,046,784

__device__ __forceinline__ unsigned long long pack2(float x) {
    unsigned long long r;
    asm("mov.b64 %0, {%1, %1};" : "=l"(r) : "f"(x));
    return r;
}
__device__ __forceinline__ void fma2(unsigned long long &d,
                                     unsigned long long a,
                                     unsigned long long b) {
    asm("fma.rn.f32x2 %0, %1, %2, %0;" : "+l"(d) : "l"(a), "l"(b));
}
__device__ __forceinline__ float2 unpack2(unsigned long long a) {
    float2 f;
    asm("mov.b64 {%0, %1}, %2;" : "=f"(f.x), "=f"(f.y) : "l"(a));
    return f;
}

__global__ __launch_bounds__(256, 1)
void stadd_kernel(const float* __restrict__ qg,
                  const float* __restrict__ kg,
                  const float* __restrict__ vg,
                  const float* __restrict__ maskg,
                  const float* __restrict__ asg,
                  const float* __restrict__ gammag,
                  const float* __restrict__ betag,
                  float* __restrict__ scores_out,
                  float* __restrict__ vout)
{
    extern __shared__ float sm[];
    const int bn   = blockIdx.x / 3;
    const int lt   = blockIdx.x % 3;
    const int l0   = lt * TL;
    const int tid  = threadIdx.x;
    const int warp = tid >> 5;      // warp == head h
    const int lane = tid & 31;
    const int h    = warp;
    const int lg   = lane >> 2;     // 0..7  (l-group of 4)
    const int sg   = lane & 3;      // 0..3  (s-group of 4 in phase 1, d-group in phase 3)

    if (tid < HDIM) { sm[GB_OFF + tid] = gammag[tid]; sm[GB_OFF + 8 + tid] = betag[tid]; }

    // ---------- Phase 0: load Q tile -> Qs[h][e][LPAD] (warp h loads its own slice)
    {
        const int l = lane;
        const float4* src = reinterpret_cast<const float4*>(
            qg + (((size_t)bn * LDIM + l0 + l) * HDIM + h) * EDIM);
        float* dst = sm + QS_OFF + h * (EDIM * LPAD) + l;
        #pragma unroll
        for (int kk = 0; kk < 16; kk++) {
            float4 f = src[kk];
            const int e = kk * 4;
            dst[(e + 0) * LPAD] = f.x;
            dst[(e + 1) * LPAD] = f.y;
            dst[(e + 2) * LPAD] = f.z;
            dst[(e + 3) * LPAD] = f.w;
        }
    }
    __syncwarp();

    // ---------- Phase 1: P[h][l][s] = Q . K   (warp-private per head)
    for (int c = 0; c < NCH; c++) {
        const int s0 = c * SC;
        // load K chunk -> Ks[h][e][KSP]; lane -> (s = lane>>1, eh = lane&1)
        {
            const int s = lane >> 1, eh = lane & 1;
            const float4* src = reinterpret_cast<const float4*>(
                kg + (((size_t)bn * SDIM + s0 + s) * HDIM + h) * EDIM + eh * 32);
            float* dst = sm + KS_OFF + h * (EDIM * KSP) + s;
            #pragma unroll
            for (int kk = 0; kk < 8; kk++) {
                float4 f = src[kk];
                const int e = eh * 32 + kk * 4;
                dst[(e + 0) * KSP] = f.x;
                dst[(e + 1) * KSP] = f.y;
                dst[(e + 2) * KSP] = f.z;
                dst[(e + 3) * KSP] = f.w;
            }
        }
        __syncwarp();

        unsigned long long acc[4][2];
        #pragma unroll
        for (int i = 0; i < 4; i++) { acc[i][0] = 0ull; acc[i][1] = 0ull; }

        const float* qb = sm + QS_OFF + h * (EDIM * LPAD) + lg * 4;
        const float* kb = sm + KS_OFF + h * (EDIM * KSP) + sg * 4;

        #pragma unroll 16
        for (int e = 0; e < EDIM; e++) {
            const float4 qv = *reinterpret_cast<const float4*>(qb + e * LPAD);
            const ulonglong2 kv = *reinterpret_cast<const ulonglong2*>(kb + e * KSP);
            unsigned long long q0 = pack2(qv.x);
            unsigned long long q1 = pack2(qv.y);
            unsigned long long q2 = pack2(qv.z);
            unsigned long long q3 = pack2(qv.w);
            fma2(acc[0][0], q0, kv.x); fma2(acc[0][1], q0, kv.y);
            fma2(acc[1][0], q1, kv.x); fma2(acc[1][1], q1, kv.y);
            fma2(acc[2][0], q2, kv.x); fma2(acc[2][1], q2, kv.y);
            fma2(acc[3][0], q3, kv.x); fma2(acc[3][1], q3, kv.y);
        }

        #pragma unroll
        for (int i = 0; i < 4; i++) {
            float* pd = sm + P_OFF + (h * TL + lg * 4 + i) * SP + s0 + sg * 4;
            float2 a = unpack2(acc[i][0]);
            float2 b = unpack2(acc[i][1]);
            pd[0] = a.x; pd[1] = a.y; pd[2] = b.x; pd[3] = b.y;
        }
        __syncwarp();
    }
    __syncthreads();

    // ---------- Phase 2: add mask + attn_scores, LayerNorm over H, write scores
    {
        const size_t as_bn = (size_t)bn * HDIM * LDIM * SDIM;
        #pragma unroll 1
        for (int it = 0; it < (TL * SDIM) / 256; it++) {
            const int idx = tid + it * 256;      // 0..3071
            const int l = idx / SDIM;
            const int s = idx - l * SDIM;
            const float mk = maskg[(l0 + l) * SDIM + s];
            const size_t base = as_bn + (size_t)(l0 + l) * SDIM + s;

            float x[8];
            float mean = 0.f;
            #pragma unroll
            for (int hh = 0; hh < 8; hh++) {
                float val = sm[P_OFF + (hh * TL + l) * SP + s] + mk
                          + asg[base + (size_t)hh * LDIM * SDIM];
                x[hh] = val;
                mean += val;
            }
            mean *= 0.125f;
            float var = 0.f;
            #pragma unroll
            for (int hh = 0; hh < 8; hh++) { float d = x[hh] - mean; var += d * d; }
            var *= 0.125f;
            const float rstd = rsqrtf(var + 1e-5f);
            #pragma unroll
            for (int hh = 0; hh < 8; hh++) {
                float sc = (x[hh] - mean) * rstd * sm[GB_OFF + hh] + sm[GB_OFF + 8 + hh];
                scores_out[base + (size_t)hh * LDIM * SDIM] = sc;
                sm[P_OFF + (hh * TL + l) * SP + s] = sc;
            }
        }
    }
    __syncthreads();

    // ---------- Softmax over s: thread -> row (h = warp, l = lane), temp = 1/sqrt(E)
    {
        float* row = sm + P_OFF + (h * TL + lane) * SP;
        float m = -3.4e38f;
        #pragma unroll 8
        for (int s = 0; s < SDIM; s++) m = fmaxf(m, row[s]);
        float sum = 0.f;
        #pragma unroll 8
        for (int s = 0; s < SDIM; s++) {
            float eo = __expf((row[s] - m) * 0.125f);
            row[s] = eo;
            sum += eo;
        }
        const float inv = 1.f / sum;
        #pragma unroll 8
        for (int s = 0; s < SDIM; s++) row[s] *= inv;
    }
    __syncwarp();

    // ---------- Phase 3: O[l][h][d] = sum_s A[l,h,s] * V[s,h,d]  (warp-private)
    {
        const int dg = sg;                 // 0..3, d0 = dg*16
        unsigned long long o[4][8];
        #pragma unroll
        for (int i = 0; i < 4; i++)
            #pragma unroll
            for (int p = 0; p < 8; p++) o[i][p] = 0ull;

        for (int c = 0; c < NCH; c++) {
            const int s0 = c * SC;
            // load V chunk -> Vs[h][s][VSP] (reuses Ks buffer, warp-private slice)
            {
                const int s = lane >> 1, eh = lane & 1;
                const float4* src = reinterpret_cast<const float4*>(
                    vg + (((size_t)bn * SDIM + s0 + s) * HDIM + h) * DDIM + eh * 32);
                float4* dst = reinterpret_cast<float4*>(
                    sm + KS_OFF + h * (SC * VSP) + s * VSP + eh * 32);
                #pragma unroll
                for (int kk = 0; kk < 8; kk++) dst[kk] = src[kk];
            }
            __syncwarp();

            const float* ab = sm + P_OFF + (h * TL + lg * 4) * SP + s0;
            const float* vb = sm + KS_OFF + h * (SC * VSP) + dg * 16;

            #pragma unroll 4
            for (int s = 0; s < SC; s++) {
                unsigned long long aa[4];
                #pragma unroll
                for (int i = 0; i < 4; i++) aa[i] = pack2(ab[i * SP + s]);

                const float* vp = vb + s * VSP;
                unsigned long long vp8[8];
                {
                    ulonglong2 t0 = *reinterpret_cast<const ulonglong2*>(vp);
                    ulonglong2 t1 = *reinterpret_cast<const ulonglong2*>(vp + 4);
                    ulonglong2 t2 = *reinterpret_cast<const ulonglong2*>(vp + 8);
                    ulonglong2 t3 = *reinterpret_cast<const ulonglong2*>(vp + 12);
                    vp8[0] = t0.x; vp8[1] = t0.y; vp8[2] = t1.x; vp8[3] = t1.y;
                    vp8[4] = t2.x; vp8[5] = t2.y; vp8[6] = t3.x; vp8[7] = t3.y;
                }
                #pragma unroll
                for (int i = 0; i < 4; i++)
                    #pragma unroll
                    for (int p = 0; p < 8; p++) fma2(o[i][p], aa[i], vp8[p]);
            }
            __syncwarp();
        }

        // write O -> vout [bn][l][h][d]
        #pragma unroll
        for (int i = 0; i < 4; i++) {
            float* dst = vout + (((size_t)bn * LDIM + l0 + lg * 4 + i) * HDIM + h) * DDIM + dg * 16;
            #pragma unroll
            for (int p2 = 0; p2 < 4; p2++) {
                float2 lo = unpack2(o[i][2 * p2]);
                float2 hi = unpack2(o[i][2 * p2 + 1]);
                float4 f = make_float4(lo.x, lo.y, hi.x, hi.y);
                *reinterpret_cast<float4*>(dst + p2 * 4) = f;
            }
        }
    }
}

extern "C" void kernel_launch(void* const* d_in, const int* in_sizes, int n_in,
                              void* d_out, int out_size) {
    const float* q     = (const float*)d_in[0];
    const float* k     = (const float*)d_in[1];
    const float* v     = (const float*)d_in[2];
    const float* mask  = (const float*)d_in[3];
    const float* ascr  = (const float*)d_in[4];
    const float* gamma = (const float*)d_in[5];
    const float* beta  = (const float*)d_in[6];
    // d_in[7], d_in[8]: query_lengths / key_lengths (constants 96), unused

    float* scores = (float*)d_out;
    float* vo     = scores + SCORES_ELEMS;

    cudaFuncSetAttribute(stadd_kernel,
                         cudaFuncAttributeMaxDynamicSharedMemorySize, SMEM_BYTES);
    stadd_kernel<<<BNTOT * 3, 256, SMEM_BYTES>>>(q, k, v, mask, ascr, gamma, beta,
                                                 scores, vo);
}

// round 9
// speedup vs baseline: 1.5083x; 1.5083x over previous
#include <cuda_runtime.h>
#include <cstdint>

// Shapes (fixed by the problem instance)
#define BNTOT 828      // B*N
#define LDIM 96
#define SDIM 96
#define HDIM 8
#define EDIM 64
#define DDIM 64

#define TL   32        // l-rows per CTA (3 tiles per bn)
#define ECH  16        // e-chunk for phase 1 (4 rounds)
#define VCHS 24        // s-chunk for phase 3 V staging (4 chunks)

// smem strides (floats) — chosen for bank-conflict-free access + 8/16B alignment
#define QST 34         // Qs[h][e'][l], rows 34
#define KST 98         // Ks[h][e'][s], rows 98
#define VST 68         // Vs[h][s][d],  rows 68
#define SP  97         // P [h][l][s],  rows 97

// smem float offsets
#define Q_OFF 0
#define Q_SZ  (HDIM*ECH*QST)             // 4352
#define K_OFF (Q_OFF + Q_SZ)
#define K_SZ  (HDIM*ECH*KST)             // 12544
#define VCH_SZ (HDIM*VCHS*VST)           // 13056 (two buffers alias Q/K region + slack)
#define P_OFF (2*VCH_SZ)                 // 26112
#define P_SZ  (HDIM*TL*SP)               // 24832
#define GB_OFF (P_OFF + P_SZ)            // 50944
#define SMEM_FLOATS (GB_OFF + 16)        // 50960
#define SMEM_BYTES  (SMEM_FLOATS * 4)    // 203840 B

#define SCORES_ELEMS ((size_t)BNTOT * HDIM * LDIM * SDIM)

typedef unsigned long long ull;

__device__ __forceinline__ ull pack2(float x) {
    ull r;
    asm("mov.b64 %0, {%1, %1};" : "=l"(r) : "f"(x));
    return r;
}
__device__ __forceinline__ void fma2(ull &d, ull a, ull b) {
    asm("fma.rn.f32x2 %0, %1, %2, %0;" : "+l"(d) : "l"(a), "l"(b));
}
__device__ __forceinline__ float2 unpack2(ull a) {
    float2 f;
    asm("mov.b64 {%0, %1}, %2;" : "=f"(f.x), "=f"(f.y) : "l"(a));
    return f;
}

__global__ __launch_bounds__(512, 1)
void stadd_kernel(const float* __restrict__ qg,
                  const float* __restrict__ kg,
                  const float* __restrict__ vg,
                  const float* __restrict__ maskg,
                  const float* __restrict__ asg,
                  const float* __restrict__ gammag,
                  const float* __restrict__ betag,
                  float* __restrict__ scores_out,
                  float* __restrict__ vout)
{
    extern __shared__ float sm[];
    const int bn   = blockIdx.x / 3;
    const int lt   = blockIdx.x % 3;
    const int l0   = lt * TL;
    const int tid  = threadIdx.x;
    const int warp = tid >> 5;
    const int lane = tid & 31;
    const int h1   = warp >> 1;   // head (2 warps per head)
    const int half = warp & 1;    // s-half in phase1, d-half in phase3
    const int lq   = lane >> 3;   // 0..3 -> 8 l rows each
    const int sq   = lane & 7;    // 0..7 -> 6 s (ph1) / 4 d (ph3)

    if (tid < HDIM) { sm[GB_OFF + tid] = gammag[tid]; sm[GB_OFF + 8 + tid] = betag[tid]; }

    // ================= Phase 1: P[h][l][s] = Q.K, e-chunked, 8l x 6s per lane
    ull acc[4][6];
    #pragma unroll
    for (int lp = 0; lp < 4; lp++)
        #pragma unroll
        for (int j = 0; j < 6; j++) acc[lp][j] = 0ull;

    float4 kreg[6], qreg[2];

    auto ldgQK = [&](int ec) {
        #pragma unroll
        for (int r = 0; r < 6; r++) {
            const int fidx = tid + r * 512;          // (h*96+s)*4+eg
            const int hh = fidx / 384;
            const int rem = fidx - hh * 384;
            const int s  = rem >> 2;
            const int eg = rem & 3;
            kreg[r] = *reinterpret_cast<const float4*>(
                kg + (((size_t)bn * SDIM + s) * HDIM + hh) * EDIM + ec * ECH + eg * 4);
        }
        #pragma unroll
        for (int r = 0; r < 2; r++) {
            const int fidx = tid + r * 512;          // (h*32+l)*4+eg
            const int hh = fidx / 128;
            const int rem = fidx - hh * 128;
            const int l  = rem >> 2;
            const int eg = rem & 3;
            qreg[r] = *reinterpret_cast<const float4*>(
                qg + (((size_t)bn * LDIM + l0 + l) * HDIM + hh) * EDIM + ec * ECH + eg * 4);
        }
    };
    auto stsQK = [&]() {
        #pragma unroll
        for (int r = 0; r < 6; r++) {
            const int fidx = tid + r * 512;
            const int hh = fidx / 384;
            const int rem = fidx - hh * 384;
            const int s  = rem >> 2;
            const int eg = rem & 3;
            float* d = sm + K_OFF + hh * (ECH * KST) + (eg * 4) * KST + s;
            d[0] = kreg[r].x; d[KST] = kreg[r].y; d[2*KST] = kreg[r].z; d[3*KST] = kreg[r].w;
        }
        #pragma unroll
        for (int r = 0; r < 2; r++) {
            const int fidx = tid + r * 512;
            const int hh = fidx / 128;
            const int rem = fidx - hh * 128;
            const int l  = rem >> 2;
            const int eg = rem & 3;
            float* d = sm + Q_OFF + hh * (ECH * QST) + (eg * 4) * QST + l;
            d[0] = qreg[r].x; d[QST] = qreg[r].y; d[2*QST] = qreg[r].z; d[3*QST] = qreg[r].w;
        }
    };

    ldgQK(0);
    const float* qb = sm + Q_OFF + h1 * (ECH * QST) + lq * 8;
    const float* kb = sm + K_OFF + h1 * (ECH * KST) + half * 48 + sq * 6;

    for (int ec = 0; ec < 4; ec++) {
        __syncthreads();          // previous round's reads finished
        stsQK();
        __syncthreads();          // staged data visible
        if (ec < 3) ldgQK(ec + 1);

        #pragma unroll 8
        for (int e = 0; e < ECH; e++) {
            const ull* qp = reinterpret_cast<const ull*>(qb + e * QST);
            const ull q0 = qp[0], q1 = qp[1], q2 = qp[2], q3 = qp[3];
            const float2* kp = reinterpret_cast<const float2*>(kb + e * KST);
            const float2 ka = kp[0], kc = kp[1], ke = kp[2];
            ull k0 = pack2(ka.x), k1 = pack2(ka.y), k2 = pack2(kc.x);
            ull k3 = pack2(kc.y), k4 = pack2(ke.x), k5 = pack2(ke.y);
            fma2(acc[0][0], q0, k0); fma2(acc[1][0], q1, k0); fma2(acc[2][0], q2, k0); fma2(acc[3][0], q3, k0);
            fma2(acc[0][1], q0, k1); fma2(acc[1][1], q1, k1); fma2(acc[2][1], q2, k1); fma2(acc[3][1], q3, k1);
            fma2(acc[0][2], q0, k2); fma2(acc[1][2], q1, k2); fma2(acc[2][2], q2, k2); fma2(acc[3][2], q3, k2);
            fma2(acc[0][3], q0, k3); fma2(acc[1][3], q1, k3); fma2(acc[2][3], q2, k3); fma2(acc[3][3], q3, k3);
            fma2(acc[0][4], q0, k4); fma2(acc[1][4], q1, k4); fma2(acc[2][4], q2, k4); fma2(acc[3][4], q3, k4);
            fma2(acc[0][5], q0, k5); fma2(acc[1][5], q1, k5); fma2(acc[2][5], q2, k5); fma2(acc[3][5], q3, k5);
        }
    }

    // store accumulators -> P  (pairs along l: stride SP rows)
    #pragma unroll
    for (int lp = 0; lp < 4; lp++) {
        #pragma unroll
        for (int j = 0; j < 6; j++) {
            float2 f = unpack2(acc[lp][j]);
            const int l = lq * 8 + lp * 2;
            const int s = half * 48 + sq * 6 + j;
            float* p = sm + P_OFF + (h1 * TL + l) * SP + s;
            p[0]  = f.x;
            p[SP] = f.y;
        }
    }
    __syncthreads();

    // ================= Phase 2: +mask +attn_scores, LayerNorm over H, write scores
    {
        const size_t as_bn = (size_t)bn * HDIM * LDIM * SDIM;
        #pragma unroll 1
        for (int it = 0; it < (TL * SDIM) / 512; it++) {
            const int idx = tid + it * 512;
            const int l = idx / SDIM;
            const int s = idx - l * SDIM;
            const float mk = maskg[(l0 + l) * SDIM + s];
            const size_t base = as_bn + (size_t)(l0 + l) * SDIM + s;

            float x[8];
            float mean = 0.f;
            #pragma unroll
            for (int hh = 0; hh < 8; hh++) {
                float val = sm[P_OFF + (hh * TL + l) * SP + s] + mk
                          + asg[base + (size_t)hh * LDIM * SDIM];
                x[hh] = val;
                mean += val;
            }
            mean *= 0.125f;
            float var = 0.f;
            #pragma unroll
            for (int hh = 0; hh < 8; hh++) { float d = x[hh] - mean; var += d * d; }
            var *= 0.125f;
            const float rstd = rsqrtf(var + 1e-5f);
            #pragma unroll
            for (int hh = 0; hh < 8; hh++) {
                float sc = (x[hh] - mean) * rstd * sm[GB_OFF + hh] + sm[GB_OFF + 8 + hh];
                scores_out[base + (size_t)hh * LDIM * SDIM] = sc;
                sm[P_OFF + (hh * TL + l) * SP + s] = sc;
            }
        }
    }
    __syncthreads();

    // ================= Softmax over s (temp = 1/8). thread -> one row (256 rows)
    if (tid < 256) {
        float* row = sm + P_OFF + tid * SP;   // (h*32+l) == tid
        float m = -3.4e38f;
        #pragma unroll 8
        for (int s = 0; s < SDIM; s++) m = fmaxf(m, row[s]);
        float sum = 0.f;
        #pragma unroll 8
        for (int s = 0; s < SDIM; s++) {
            float eo = __expf((row[s] - m) * 0.125f);
            row[s] = eo;
            sum += eo;
        }
        const float inv = 1.f / sum;
        #pragma unroll 8
        for (int s = 0; s < SDIM; s++) row[s] *= inv;
    }
    __syncthreads();

    // ================= Phase 3: O = A.V, warp=(h, d-half), 8l x 4d per lane
    {
        ull o[8][2];
        #pragma unroll
        for (int i = 0; i < 8; i++) { o[i][0] = 0ull; o[i][1] = 0ull; }

        float4 vreg[6];
        auto ldgV = [&](int c) {
            #pragma unroll
            for (int r = 0; r < 6; r++) {
                const int fidx = tid + r * 512;      // (h*24+s)*16+dg
                const int hh = fidx / 384;
                const int rem = fidx - hh * 384;
                const int s  = rem >> 4;
                const int dg = rem & 15;
                vreg[r] = *reinterpret_cast<const float4*>(
                    vg + (((size_t)bn * SDIM + c * VCHS + s) * HDIM + hh) * DDIM + dg * 4);
            }
        };
        auto stsV = [&](int buf) {
            #pragma unroll
            for (int r = 0; r < 6; r++) {
                const int fidx = tid + r * 512;
                const int hh = fidx / 384;
                const int rem = fidx - hh * 384;
                const int s  = rem >> 4;
                const int dg = rem & 15;
                *reinterpret_cast<float4*>(
                    sm + buf * VCH_SZ + hh * (VCHS * VST) + s * VST + dg * 4) = vreg[r];
            }
        };

        ldgV(0);
        const float* ab0 = sm + P_OFF + (h1 * TL + lq * 8) * SP;
        for (int c = 0; c < 4; c++) {
            stsV(c & 1);
            __syncthreads();
            if (c < 3) ldgV(c + 1);

            const float* ab = ab0 + c * VCHS;
            const float* vb = sm + (c & 1) * VCH_SZ + h1 * (VCHS * VST) + half * 32 + sq * 4;

            #pragma unroll 4
            for (int ss = 0; ss < VCHS; ss++) {
                ull aa[8];
                #pragma unroll
                for (int i = 0; i < 8; i++) aa[i] = pack2(ab[i * SP + ss]);
                const ulonglong2 vv = *reinterpret_cast<const ulonglong2*>(vb + ss * VST);
                #pragma unroll
                for (int i = 0; i < 8; i++) {
                    fma2(o[i][0], aa[i], vv.x);
                    fma2(o[i][1], aa[i], vv.y);
                }
            }
        }

        // write O -> vout [bn][l][h][d]
        #pragma unroll
        for (int i = 0; i < 8; i++) {
            float2 r0 = unpack2(o[i][0]);
            float2 r1 = unpack2(o[i][1]);
            float4 f = make_float4(r0.x, r0.y, r1.x, r1.y);
            *reinterpret_cast<float4*>(
                vout + (((size_t)bn * LDIM + l0 + lq * 8 + i) * HDIM + h1) * DDIM
                     + half * 32 + sq * 4) = f;
        }
    }
}

extern "C" void kernel_launch(void* const* d_in, const int* in_sizes, int n_in,
                              void* d_out, int out_size) {
    const float* q     = (const float*)d_in[0];
    const float* k     = (const float*)d_in[1];
    const float* v     = (const float*)d_in[2];
    const float* mask  = (const float*)d_in[3];
    const float* ascr  = (const float*)d_in[4];
    const float* gamma = (const float*)d_in[5];
    const float* beta  = (const float*)d_in[6];

    float* scores = (float*)d_out;
    float* vo     = scores + SCORES_ELEMS;

    cudaFuncSetAttribute(stadd_kernel,
                         cudaFuncAttributeMaxDynamicSharedMemorySize, SMEM_BYTES);
    stadd_kernel<<<BNTOT * 3, 512, SMEM_BYTES>>>(q, k, v, mask, ascr, gamma, beta,
                                                 scores, vo);
}